// round 1
// baseline (speedup 1.0000x reference)
#include <cuda_runtime.h>
#include <cuda_bf16.h>
#include <math.h>

typedef unsigned long long ull;

// ---------------- device scratch (no allocs allowed) ----------------
__device__ float g_X[64 * 1024];      // padded inputs (rows 50..63 zero)
__device__ float g_Gin[50 * 4096];    // W_ih @ x_t + b_ih + b_hh, per step
__device__ float g_HS[64 * 1024];     // h_t history (rows 50..63 stay zero)
__device__ float g_c[1024];           // cell state

// ---------------- f32x2 helpers ----------------
__device__ __forceinline__ ull pack2(float x, float y) {
    ull r;
    asm("mov.b64 %0, {%1, %2};" : "=l"(r) : "f"(x), "f"(y));
    return r;
}
__device__ __forceinline__ void ffma2(ull& d, ull a, ull b) {
    asm("fma.rn.f32x2 %0, %1, %2, %0;" : "+l"(d) : "l"(a), "l"(b));
}

// ---------------- prep: gather X rows, zero pads, copy c0 ----------------
__global__ void prep_kernel(const int* __restrict__ sent,
                            const float* __restrict__ emb,
                            const float* __restrict__ c0) {
    int b = blockIdx.x;
    int tid = threadIdx.x;  // 256 threads, float4 each -> 1024 floats
    if (b < 64) {
        float4* dst = (float4*)(g_X + b * 1024);
        if (b < 50) {
            int row = (b == 0) ? 1 : sent[b - 1];  // START_ID = 1
            const float4* src = (const float4*)(emb + (size_t)row * 1024);
            dst[tid] = src[tid];
        } else {
            float4 z = make_float4(0.f, 0.f, 0.f, 0.f);
            dst[tid] = z;
            ((float4*)(g_HS + b * 1024))[tid] = z;  // keep GEMM pad rows zero
        }
    } else {
        ((float4*)g_c)[tid] = ((const float4*)c0)[tid];
    }
}

// ---------------- tiled fp32 GEMM: C[m][n] = A[m][:] . W[n][:] + bias ----------------
// A: [64][K] row-major (rows >= Mvalid are zero). W: [N][K] row-major.
// BM=64, BN=128, BK=16, 128 threads, 8x8 thread tile, f32x2 accumulation.
#define GBM 64
#define GBN 128
#define GBK 16
__global__ __launch_bounds__(128) void gemm_kernel(
    const float* __restrict__ A, const float* __restrict__ W,
    const float* __restrict__ bias1, const float* __restrict__ bias2,
    float* __restrict__ C, int Mvalid, int N, int K, int ldc) {
    __shared__ float sA[GBK][GBM];
    __shared__ float sB[GBK][GBN];

    const int tid = threadIdx.x;
    const int tn = tid & 15;   // 0..15 -> n0 = tn*8
    const int tm = tid >> 4;   // 0..7  -> m0 = tm*8
    const int n_block = blockIdx.x * GBN;

    ull acc[8][4];
#pragma unroll
    for (int i = 0; i < 8; i++)
#pragma unroll
        for (int p = 0; p < 4; p++) acc[i][p] = 0ULL;

    for (int k0 = 0; k0 < K; k0 += GBK) {
        // load A tile (64x16) transposed into sA[k][m]
#pragma unroll
        for (int s = 0; s < 2; s++) {
            int idx = s * 128 + tid;
            int m = idx & 63;
            int kg = idx >> 6;  // 0..3
            float4 v = *(const float4*)(A + (size_t)m * K + k0 + kg * 4);
            sA[kg * 4 + 0][m] = v.x;
            sA[kg * 4 + 1][m] = v.y;
            sA[kg * 4 + 2][m] = v.z;
            sA[kg * 4 + 3][m] = v.w;
        }
        // load B tile (128x16) transposed into sB[k][n]
#pragma unroll
        for (int s = 0; s < 4; s++) {
            int idx = s * 128 + tid;
            int n = idx & 127;
            int kg = idx >> 7;  // 0..3
            int gn = n_block + n;
            float4 v = make_float4(0.f, 0.f, 0.f, 0.f);
            if (gn < N) v = *(const float4*)(W + (size_t)gn * K + k0 + kg * 4);
            sB[kg * 4 + 0][n] = v.x;
            sB[kg * 4 + 1][n] = v.y;
            sB[kg * 4 + 2][n] = v.z;
            sB[kg * 4 + 3][n] = v.w;
        }
        __syncthreads();

#pragma unroll
        for (int k = 0; k < GBK; k++) {
            const float* ar = &sA[k][tm * 8];
            float4 a0 = *(const float4*)ar;
            float4 a1 = *(const float4*)(ar + 4);
            const ull* br = (const ull*)&sB[k][tn * 8];
            ull b0 = br[0], b1 = br[1], b2 = br[2], b3 = br[3];
            ull ap[8];
            ap[0] = pack2(a0.x, a0.x);
            ap[1] = pack2(a0.y, a0.y);
            ap[2] = pack2(a0.z, a0.z);
            ap[3] = pack2(a0.w, a0.w);
            ap[4] = pack2(a1.x, a1.x);
            ap[5] = pack2(a1.y, a1.y);
            ap[6] = pack2(a1.z, a1.z);
            ap[7] = pack2(a1.w, a1.w);
#pragma unroll
            for (int i = 0; i < 8; i++) {
                ffma2(acc[i][0], ap[i], b0);
                ffma2(acc[i][1], ap[i], b1);
                ffma2(acc[i][2], ap[i], b2);
                ffma2(acc[i][3], ap[i], b3);
            }
        }
        __syncthreads();
    }

    // epilogue
#pragma unroll
    for (int i = 0; i < 8; i++) {
        int m = tm * 8 + i;
        if (m >= Mvalid) break;
        float* crow = C + (size_t)m * ldc;
#pragma unroll
        for (int p = 0; p < 4; p++) {
            float2 v = *(float2*)&acc[i][p];
            int n = n_block + tn * 8 + p * 2;
            if (n < N) {
                float b = bias1[n] + (bias2 ? bias2[n] : 0.f);
                crow[n] = v.x + b;
            }
            if (n + 1 < N) {
                float b = bias1[n + 1] + (bias2 ? bias2[n + 1] : 0.f);
                crow[n + 1] = v.y + b;
            }
        }
    }
}

// ---------------- one LSTM step: block j computes 4 gate dots + update ----------------
__global__ __launch_bounds__(128) void lstm_step_kernel(
    const float* __restrict__ Whh,   // [4096][1024]
    const float* __restrict__ gin,   // Gin row for this t: [4096]
    const float* __restrict__ h_in,  // [1024]
    float* __restrict__ h_out,       // HS row t
    float* __restrict__ c) {         // [1024]
    int j = blockIdx.x;
    int warp = threadIdx.x >> 5;  // gate index 0..3 (i,f,g,o)
    int lane = threadIdx.x & 31;

    const float4* wrow = (const float4*)(Whh + ((size_t)(warp * 1024 + j)) * 1024);
    const float4* hv = (const float4*)h_in;

    float sum = 0.f;
#pragma unroll
    for (int i = 0; i < 8; i++) {
        float4 w = wrow[lane + i * 32];
        float4 h4 = hv[lane + i * 32];
        sum += w.x * h4.x + w.y * h4.y + w.z * h4.z + w.w * h4.w;
    }
#pragma unroll
    for (int off = 16; off; off >>= 1) sum += __shfl_down_sync(0xFFFFFFFFu, sum, off);

    __shared__ float sg[4];
    if (lane == 0) sg[warp] = sum + gin[warp * 1024 + j];
    __syncthreads();

    if (threadIdx.x == 0) {
        float ig = 1.f / (1.f + expf(-sg[0]));
        float fg = 1.f / (1.f + expf(-sg[1]));
        float gg = tanhf(sg[2]);
        float og = 1.f / (1.f + expf(-sg[3]));
        float cn = fg * c[j] + ig * gg;
        c[j] = cn;
        h_out[j] = og * tanhf(cn);
    }
}

// ---------------- launch ----------------
extern "C" void kernel_launch(void* const* d_in, const int* in_sizes, int n_in,
                              void* d_out, int out_size) {
    const int* sent = (const int*)d_in[0];
    const float* h0 = (const float*)d_in[1];
    const float* c0 = (const float*)d_in[2];
    const float* emb = (const float*)d_in[3];
    const float* Wih = (const float*)d_in[4];
    const float* Whh = (const float*)d_in[5];
    const float* bih = (const float*)d_in[6];
    const float* bhh = (const float*)d_in[7];
    const float* Wout = (const float*)d_in[8];
    const float* bout = (const float*)d_in[9];
    float* out = (float*)d_out;

    float* gX;
    float* gGin;
    float* gHS;
    float* gC;
    cudaGetSymbolAddress((void**)&gX, g_X);
    cudaGetSymbolAddress((void**)&gGin, g_Gin);
    cudaGetSymbolAddress((void**)&gHS, g_HS);
    cudaGetSymbolAddress((void**)&gC, g_c);

    // 1) gather inputs + init state
    prep_kernel<<<65, 256>>>(sent, emb, c0);

    // 2) input projection for all 50 steps: Gin = X @ W_ih^T + b_ih + b_hh
    gemm_kernel<<<4096 / GBN, 128>>>(gX, Wih, bih, bhh, gGin, 50, 4096, 1024, 4096);

    // 3) sequential recurrence
    for (int t = 0; t < 50; t++) {
        const float* hin = (t == 0) ? h0 : (gHS + (size_t)(t - 1) * 1024);
        lstm_step_kernel<<<1024, 128>>>(Whh, gGin + (size_t)t * 4096, hin,
                                        gHS + (size_t)t * 1024, gC);
    }

    // 4) output projection: logits = HS @ W_out^T + b_out
    gemm_kernel<<<(50257 + GBN - 1) / GBN, 128>>>(gHS, Wout, bout, nullptr, out,
                                                  50, 50257, 1024, 50257);
}

// round 2
// speedup vs baseline: 1.0860x; 1.0860x over previous
#include <cuda_runtime.h>
#include <cuda_bf16.h>
#include <math.h>

typedef unsigned long long ull;

#define NBLK 128
#define NSTEP 50

// ---------------- device scratch (no allocs allowed) ----------------
__device__ float g_X[64 * 1024];      // padded inputs (rows 50..63 zero)
__device__ float g_Gin[50 * 4096];    // W_ih @ x_t + b_ih + b_hh, per step
__device__ float g_HS[64 * 1024];     // h_t history (rows 50..63 stay zero)
__device__ float g_h[2][1024];        // double-buffered hidden state
__device__ unsigned g_arrive;         // cumulative grid-barrier counter

// ---------------- f32x2 helpers ----------------
__device__ __forceinline__ ull pack2(float x, float y) {
    ull r;
    asm("mov.b64 %0, {%1, %2};" : "=l"(r) : "f"(x), "f"(y));
    return r;
}
__device__ __forceinline__ void ffma2(ull& d, ull a, ull b) {
    asm("fma.rn.f32x2 %0, %1, %2, %0;" : "+l"(d) : "l"(a), "l"(b));
}
__device__ __forceinline__ float sum2(ull a) {
    float2 v = *(float2*)&a;
    return v.x + v.y;
}

// ---------------- prep: gather X rows, zero pads, init state, reset barrier ----------------
__global__ void prep_kernel(const int* __restrict__ sent,
                            const float* __restrict__ emb,
                            const float* __restrict__ h0) {
    int b = blockIdx.x;
    int tid = threadIdx.x;  // 256 threads, float4 each -> 1024 floats
    if (b < 64) {
        float4* dst = (float4*)(g_X + b * 1024);
        if (b < 50) {
            int row = (b == 0) ? 1 : sent[b - 1];  // START_ID = 1
            const float4* src = (const float4*)(emb + (size_t)row * 1024);
            dst[tid] = src[tid];
        } else {
            float4 z = make_float4(0.f, 0.f, 0.f, 0.f);
            dst[tid] = z;
            ((float4*)(g_HS + b * 1024))[tid] = z;  // keep GEMM pad rows zero
        }
    } else {
        // copy h0 into g_h[0], reset barrier counter
        ((float4*)g_h[0])[tid] = ((const float4*)h0)[tid];
        if (tid == 0) g_arrive = 0u;
    }
}

// ---------------- tiled fp32 GEMM: C[m][n] = A[m][:] . W[n][:] + bias ----------------
#define GBM 64
#define GBN 128
#define GBK 16
__global__ __launch_bounds__(128) void gemm_kernel(
    const float* __restrict__ A, const float* __restrict__ W,
    const float* __restrict__ bias1, const float* __restrict__ bias2,
    float* __restrict__ C, int Mvalid, int N, int K, int ldc) {
    __shared__ float sA[GBK][GBM];
    __shared__ float sB[GBK][GBN];

    const int tid = threadIdx.x;
    const int tn = tid & 15;
    const int tm = tid >> 4;
    const int n_block = blockIdx.x * GBN;

    ull acc[8][4];
#pragma unroll
    for (int i = 0; i < 8; i++)
#pragma unroll
        for (int p = 0; p < 4; p++) acc[i][p] = 0ULL;

    for (int k0 = 0; k0 < K; k0 += GBK) {
#pragma unroll
        for (int s = 0; s < 2; s++) {
            int idx = s * 128 + tid;
            int m = idx & 63;
            int kg = idx >> 6;
            float4 v = *(const float4*)(A + (size_t)m * K + k0 + kg * 4);
            sA[kg * 4 + 0][m] = v.x;
            sA[kg * 4 + 1][m] = v.y;
            sA[kg * 4 + 2][m] = v.z;
            sA[kg * 4 + 3][m] = v.w;
        }
#pragma unroll
        for (int s = 0; s < 4; s++) {
            int idx = s * 128 + tid;
            int n = idx & 127;
            int kg = idx >> 7;
            int gn = n_block + n;
            float4 v = make_float4(0.f, 0.f, 0.f, 0.f);
            if (gn < N) v = *(const float4*)(W + (size_t)gn * K + k0 + kg * 4);
            sB[kg * 4 + 0][n] = v.x;
            sB[kg * 4 + 1][n] = v.y;
            sB[kg * 4 + 2][n] = v.z;
            sB[kg * 4 + 3][n] = v.w;
        }
        __syncthreads();

#pragma unroll
        for (int k = 0; k < GBK; k++) {
            const float* ar = &sA[k][tm * 8];
            float4 a0 = *(const float4*)ar;
            float4 a1 = *(const float4*)(ar + 4);
            const ull* br = (const ull*)&sB[k][tn * 8];
            ull b0 = br[0], b1 = br[1], b2 = br[2], b3 = br[3];
            ull ap[8];
            ap[0] = pack2(a0.x, a0.x);
            ap[1] = pack2(a0.y, a0.y);
            ap[2] = pack2(a0.z, a0.z);
            ap[3] = pack2(a0.w, a0.w);
            ap[4] = pack2(a1.x, a1.x);
            ap[5] = pack2(a1.y, a1.y);
            ap[6] = pack2(a1.z, a1.z);
            ap[7] = pack2(a1.w, a1.w);
#pragma unroll
            for (int i = 0; i < 8; i++) {
                ffma2(acc[i][0], ap[i], b0);
                ffma2(acc[i][1], ap[i], b1);
                ffma2(acc[i][2], ap[i], b2);
                ffma2(acc[i][3], ap[i], b3);
            }
        }
        __syncthreads();
    }

#pragma unroll
    for (int i = 0; i < 8; i++) {
        int m = tm * 8 + i;
        if (m >= Mvalid) break;
        float* crow = C + (size_t)m * ldc;
#pragma unroll
        for (int p = 0; p < 4; p++) {
            float2 v = *(float2*)&acc[i][p];
            int n = n_block + tn * 8 + p * 2;
            if (n < N) {
                float b = bias1[n] + (bias2 ? bias2[n] : 0.f);
                crow[n] = v.x + b;
            }
            if (n + 1 < N) {
                float b = bias1[n + 1] + (bias2 ? bias2[n + 1] : 0.f);
                crow[n + 1] = v.y + b;
            }
        }
    }
}

// ---------------- persistent LSTM recurrence ----------------
// 128 blocks x 256 threads, all co-resident (1 block/SM).
// Block b owns hidden units j in [b*8, b*8+8): 32 gate-rows of W_hh,
// held entirely in registers (128 floats/thread).
// Thread (warp w, r=lane>>3, c=lane&7): row rid=w*4+r, cols {it*32 + c*4 .. +3}.
__global__ __launch_bounds__(256, 1) void lstm_persistent(
    const float* __restrict__ Whh,      // [4096][1024]
    const float* __restrict__ gin_all,  // [50][4096]
    const float* __restrict__ c0) {     // [1024]
    const int b = blockIdx.x;
    const int tid = threadIdx.x;
    const int w = tid >> 5;
    const int lane = tid & 31;
    const int r = lane >> 3;
    const int c = lane & 7;
    const int rid = w * 4 + r;           // 0..31
    const int gate = rid >> 3;           // 0..3
    const int jj = rid & 7;              // 0..7
    const int grow = gate * 1024 + b * 8 + jj;

    // Load this thread's W_hh slice into registers (interleaved cols).
    float4 Wreg[32];
    const float4* wp = (const float4*)(Whh + (size_t)grow * 1024);
#pragma unroll
    for (int it = 0; it < 32; it++) Wreg[it] = wp[it * 8 + c];

    __shared__ float4 h_s[256];  // h staged per step
    __shared__ float sg[32];     // per-row gate sums
    __shared__ float c_s[8];     // cell state for this block's units
    if (tid < 8) c_s[tid] = c0[b * 8 + tid];

    for (int t = 0; t < NSTEP; t++) {
        // stage h (previous barrier / prep guarantees g_h[t&1] is ready)
        h_s[tid] = ((const float4*)g_h[t & 1])[tid];
        __syncthreads();

        ull a0 = 0, a1 = 0, a2 = 0, a3 = 0;
#pragma unroll
        for (int it = 0; it < 32; it++) {
            float4 h4 = h_s[it * 8 + c];  // broadcast to 4 row-lanes, conflict-free
            float4 w4 = Wreg[it];
            ull hx = pack2(h4.x, h4.y);
            ull hy = pack2(h4.z, h4.w);
            ull wx = pack2(w4.x, w4.y);
            ull wy = pack2(w4.z, w4.w);
            if (it & 1) {
                ffma2(a2, wx, hx);
                ffma2(a3, wy, hy);
            } else {
                ffma2(a0, wx, hx);
                ffma2(a1, wy, hy);
            }
        }
        float sum = (sum2(a0) + sum2(a1)) + (sum2(a2) + sum2(a3));
        // reduce across the 8 chunk-lanes (same row)
        sum += __shfl_xor_sync(0xFFFFFFFFu, sum, 1);
        sum += __shfl_xor_sync(0xFFFFFFFFu, sum, 2);
        sum += __shfl_xor_sync(0xFFFFFFFFu, sum, 4);
        if (c == 0) sg[rid] = sum;
        __syncthreads();

        if (tid < 8) {
            const int j = tid;
            const float* gin = gin_all + (size_t)t * 4096 + b * 8 + j;
            float vi = sg[0 * 8 + j] + gin[0];
            float vf = sg[1 * 8 + j] + gin[1024];
            float vg = sg[2 * 8 + j] + gin[2048];
            float vo = sg[3 * 8 + j] + gin[3072];
            float ig = 1.f / (1.f + expf(-vi));
            float fg = 1.f / (1.f + expf(-vf));
            float gg = tanhf(vg);
            float og = 1.f / (1.f + expf(-vo));
            float cn = fg * c_s[j] + ig * gg;
            c_s[j] = cn;
            float hn = og * tanhf(cn);
            g_h[(t + 1) & 1][b * 8 + j] = hn;
            g_HS[(size_t)t * 1024 + b * 8 + j] = hn;
            __threadfence();  // make h visible GPU-wide before arrival
        }
        __syncthreads();

        // grid barrier: cumulative counter, target = NBLK*(t+1)
        if (tid == 0) {
            atomicAdd(&g_arrive, 1u);
            const unsigned target = (unsigned)NBLK * (unsigned)(t + 1);
            unsigned v;
            do {
                asm volatile("ld.global.acquire.gpu.u32 %0, [%1];"
                             : "=r"(v) : "l"(&g_arrive));
            } while (v < target);
        }
        __syncthreads();
    }
}

// ---------------- launch ----------------
extern "C" void kernel_launch(void* const* d_in, const int* in_sizes, int n_in,
                              void* d_out, int out_size) {
    const int* sent = (const int*)d_in[0];
    const float* h0 = (const float*)d_in[1];
    const float* c0 = (const float*)d_in[2];
    const float* emb = (const float*)d_in[3];
    const float* Wih = (const float*)d_in[4];
    const float* Whh = (const float*)d_in[5];
    const float* bih = (const float*)d_in[6];
    const float* bhh = (const float*)d_in[7];
    const float* Wout = (const float*)d_in[8];
    const float* bout = (const float*)d_in[9];
    float* out = (float*)d_out;

    float* gX;
    float* gGin;
    float* gHS;
    cudaGetSymbolAddress((void**)&gX, g_X);
    cudaGetSymbolAddress((void**)&gGin, g_Gin);
    cudaGetSymbolAddress((void**)&gHS, g_HS);

    // 1) gather inputs + init state + reset barrier
    prep_kernel<<<65, 256>>>(sent, emb, h0);

    // 2) input projection for all 50 steps: Gin = X @ W_ih^T + b_ih + b_hh
    gemm_kernel<<<4096 / GBN, 128>>>(gX, Wih, bih, bhh, gGin, 50, 4096, 1024, 4096);

    // 3) persistent recurrence (single launch, register-resident W_hh)
    lstm_persistent<<<NBLK, 256>>>(Whh, gGin, c0);

    // 4) output projection: logits = HS @ W_out^T + b_out
    gemm_kernel<<<(50257 + GBN - 1) / GBN, 128>>>(gHS, Wout, bout, nullptr, out,
                                                  50, 50257, 1024, 50257);
}

// round 3
// speedup vs baseline: 1.3133x; 1.2093x over previous
#include <cuda_runtime.h>
#include <cuda_bf16.h>
#include <math.h>

typedef unsigned long long ull;

#define NBLK 128
#define NSTEP 50
#define LDP_OUT 50304   // 393*128, padded ld for partials
#define NOUT 50257

// ---------------- device scratch (no allocs allowed) ----------------
__device__ float g_X[64 * 1024];          // padded inputs (rows 50..63 zero)
__device__ float g_Gin[50 * 4096];        // W_ih @ x_t + b_ih + b_hh
__device__ float g_HS[64 * 1024];         // h_t history (rows 50..63 zero)
__device__ float g_h[2][1024];            // double-buffered hidden state
__device__ unsigned g_arrive;             // cumulative grid-barrier counter
__device__ float g_P[2 * 64 * LDP_OUT];   // split-K partial buffers (reused)

// ---------------- helpers ----------------
__device__ __forceinline__ ull pack2(float x, float y) {
    ull r;
    asm("mov.b64 %0, {%1, %2};" : "=l"(r) : "f"(x), "f"(y));
    return r;
}
__device__ __forceinline__ void ffma2(ull& d, ull a, ull b) {
    asm("fma.rn.f32x2 %0, %1, %2, %0;" : "+l"(d) : "l"(a), "l"(b));
}
__device__ __forceinline__ float sum2(ull a) {
    float2 v = *(float2*)&a;
    return v.x + v.y;
}
__device__ __forceinline__ void red_release_add1(unsigned* p) {
    asm volatile("red.release.gpu.global.add.u32 [%0], 1;" :: "l"(p) : "memory");
}
__device__ __forceinline__ unsigned ld_acquire(const unsigned* p) {
    unsigned v;
    asm volatile("ld.acquire.gpu.global.u32 %0, [%1];" : "=r"(v) : "l"(p) : "memory");
    return v;
}

// ---------------- prep: gather X rows, zero pads, init state, reset barrier ----------------
__global__ void prep_kernel(const int* __restrict__ sent,
                            const float* __restrict__ emb,
                            const float* __restrict__ h0) {
    int b = blockIdx.x;
    int tid = threadIdx.x;  // 256 threads, float4 each -> 1024 floats
    if (b < 64) {
        float4* dst = (float4*)(g_X + b * 1024);
        if (b < 50) {
            int row = (b == 0) ? 1 : sent[b - 1];  // START_ID = 1
            const float4* src = (const float4*)(emb + (size_t)row * 1024);
            dst[tid] = src[tid];
        } else {
            float4 z = make_float4(0.f, 0.f, 0.f, 0.f);
            dst[tid] = z;
            ((float4*)(g_HS + b * 1024))[tid] = z;  // keep GEMM pad rows zero
        }
    } else {
        ((float4*)g_h[0])[tid] = ((const float4*)h0)[tid];
        if (tid == 0) g_arrive = 0u;
    }
}

// ---------------- split-K GEMM: P[ks][m][n] = A[m][kbeg:kend] . W[n][kbeg:kend] ----------------
// A: [64][K] row-major. W: [N][K] row-major. P: [nsplit][64][ldp].
// BM=64, BN=128, BK=16, 128 threads, 8x8 thread tiles, f32x2, smem double-buffered.
__global__ __launch_bounds__(128) void gemm_splitk(
    const float* __restrict__ A, const float* __restrict__ W,
    float* __restrict__ P, int N, int K, int ldp, int nsplit) {
    __shared__ ull sAd[2][16][64];     // A duplicated as (a,a) pairs
    __shared__ float sB[2][16][128];

    const int tid = threadIdx.x;
    const int tn = tid & 15;   // n0 = tn*8
    const int tm = tid >> 4;   // m0 = tm*8
    const int n_block = blockIdx.x * 128;
    const int klen = K / nsplit;
    const int kbeg = blockIdx.y * klen;
    const int nk = klen / 16;
    float* Pp = P + (size_t)blockIdx.y * 64 * ldp;

    ull acc[8][4];
#pragma unroll
    for (int i = 0; i < 8; i++)
#pragma unroll
        for (int p = 0; p < 4; p++) acc[i][p] = 0ULL;

    const int mA = tid & 63;
    const int kgA = tid >> 6;          // 0..1 (with s offset -> 0..3)
    const int nB = tid & 127;

    float4 ra[2], rb[4];
    // prologue: load tile 0
#pragma unroll
    for (int s = 0; s < 2; s++) {
        int kg = kgA + s * 2;
        ra[s] = *(const float4*)(A + (size_t)mA * K + kbeg + kg * 4);
    }
#pragma unroll
    for (int s = 0; s < 4; s++) {
        int kg = s;
        int gn = n_block + nB;
        rb[s] = make_float4(0.f, 0.f, 0.f, 0.f);
        if (gn < N) rb[s] = *(const float4*)(W + (size_t)gn * K + kbeg + kg * 4);
    }
    // store tile 0
    {
#pragma unroll
        for (int s = 0; s < 2; s++) {
            int kg = kgA + s * 2;
            sAd[0][kg * 4 + 0][mA] = pack2(ra[s].x, ra[s].x);
            sAd[0][kg * 4 + 1][mA] = pack2(ra[s].y, ra[s].y);
            sAd[0][kg * 4 + 2][mA] = pack2(ra[s].z, ra[s].z);
            sAd[0][kg * 4 + 3][mA] = pack2(ra[s].w, ra[s].w);
        }
#pragma unroll
        for (int s = 0; s < 4; s++) {
            sB[0][s * 4 + 0][nB] = rb[s].x;
            sB[0][s * 4 + 1][nB] = rb[s].y;
            sB[0][s * 4 + 2][nB] = rb[s].z;
            sB[0][s * 4 + 3][nB] = rb[s].w;
        }
    }
    __syncthreads();

    for (int kt = 0; kt < nk; kt++) {
        const int buf = kt & 1;
        // prefetch next tile into regs (latency hidden by compute below)
        if (kt + 1 < nk) {
            int kp = kbeg + (kt + 1) * 16;
#pragma unroll
            for (int s = 0; s < 2; s++) {
                int kg = kgA + s * 2;
                ra[s] = *(const float4*)(A + (size_t)mA * K + kp + kg * 4);
            }
#pragma unroll
            for (int s = 0; s < 4; s++) {
                int gn = n_block + nB;
                rb[s] = make_float4(0.f, 0.f, 0.f, 0.f);
                if (gn < N) rb[s] = *(const float4*)(W + (size_t)gn * K + kp + s * 4);
            }
        }
        // compute on current buffer
#pragma unroll
        for (int k = 0; k < 16; k++) {
            const ull* ap = &sAd[buf][k][tm * 8];
            const ull* bp = (const ull*)&sB[buf][k][tn * 8];
            ull b0 = bp[0], b1 = bp[1], b2 = bp[2], b3 = bp[3];
#pragma unroll
            for (int i = 0; i < 8; i++) {
                ull ai = ap[i];
                ffma2(acc[i][0], ai, b0);
                ffma2(acc[i][1], ai, b1);
                ffma2(acc[i][2], ai, b2);
                ffma2(acc[i][3], ai, b3);
            }
        }
        // store next tile to other buffer
        if (kt + 1 < nk) {
            const int nb = buf ^ 1;
#pragma unroll
            for (int s = 0; s < 2; s++) {
                int kg = kgA + s * 2;
                sAd[nb][kg * 4 + 0][mA] = pack2(ra[s].x, ra[s].x);
                sAd[nb][kg * 4 + 1][mA] = pack2(ra[s].y, ra[s].y);
                sAd[nb][kg * 4 + 2][mA] = pack2(ra[s].z, ra[s].z);
                sAd[nb][kg * 4 + 3][mA] = pack2(ra[s].w, ra[s].w);
            }
#pragma unroll
            for (int s = 0; s < 4; s++) {
                sB[nb][s * 4 + 0][nB] = rb[s].x;
                sB[nb][s * 4 + 1][nB] = rb[s].y;
                sB[nb][s * 4 + 2][nB] = rb[s].z;
                sB[nb][s * 4 + 3][nB] = rb[s].w;
            }
            __syncthreads();
        }
    }

    // epilogue: vectorized stores into padded partial buffer (all 64 rows)
#pragma unroll
    for (int i = 0; i < 8; i++) {
        int m = tm * 8 + i;
        float4* dst = (float4*)(Pp + (size_t)m * ldp + n_block + tn * 8);
        dst[0] = *(float4*)&acc[i][0];
        dst[1] = *(float4*)&acc[i][2];
    }
}

// ---------------- combine: out = P0 + P1 + bias ----------------
__global__ void combine_out_kernel(const float* __restrict__ bout,
                                   float* __restrict__ out) {
    int m = blockIdx.y;
    int n = blockIdx.x * 256 + threadIdx.x;
    if (n < NOUT) {
        size_t po = (size_t)m * LDP_OUT + n;
        out[(size_t)m * NOUT + n] = g_P[po] + g_P[(size_t)64 * LDP_OUT + po] + bout[n];
    }
}

// ---------------- combine: Gin = P0+P1+P2+P3 + bih + bhh ----------------
__global__ void combine_gin_kernel(const float* __restrict__ bih,
                                   const float* __restrict__ bhh) {
    int m = blockIdx.y;  // 0..49
    int n = blockIdx.x * 256 + threadIdx.x;  // 0..4095
    float s = bih[n] + bhh[n];
#pragma unroll
    for (int sp = 0; sp < 4; sp++) s += g_P[(size_t)sp * 64 * 4096 + (size_t)m * 4096 + n];
    g_Gin[(size_t)m * 4096 + n] = s;
}

// ---------------- persistent LSTM recurrence ----------------
// 128 blocks x 256 threads (1/SM). Block b owns units [b*8, b*8+8).
// Thread (w, r=lane>>3, c=lane&7): gate-row rid=w*4+r, cols {it*32 + c*4..+3}.
__global__ __launch_bounds__(256, 1) void lstm_persistent(
    const float* __restrict__ Whh,      // [4096][1024]
    const float* __restrict__ gin_all,  // [50][4096]
    const float* __restrict__ c0) {     // [1024]
    const int b = blockIdx.x;
    const int tid = threadIdx.x;
    const int w = tid >> 5;
    const int lane = tid & 31;
    const int r = lane >> 3;
    const int c = lane & 7;
    const int rid = w * 4 + r;           // 0..31
    const int gate = rid >> 3;           // 0..3
    const int jj = rid & 7;              // 0..7
    const int grow = gate * 1024 + b * 8 + jj;

    __shared__ float4 h_s[256];
    __shared__ float sg[32];
    __shared__ float c_s[8];
    __shared__ float sGin[NSTEP][4][8];  // this block's Gin slice, all steps

    // preload Gin slice: 200 segments of 8 floats
    if (tid < 200) {
        int t = tid >> 2, g = tid & 3;
        const float4* src = (const float4*)(gin_all + (size_t)t * 4096 + g * 1024 + b * 8);
        ((float4*)&sGin[t][g][0])[0] = src[0];
        ((float4*)&sGin[t][g][0])[1] = src[1];
    }
    if (tid < 8) c_s[tid] = c0[b * 8 + tid];

    // W_hh slice into registers (interleaved cols, coalesced)
    float4 Wreg[32];
    const float4* wp = (const float4*)(Whh + (size_t)grow * 1024);
#pragma unroll
    for (int it = 0; it < 32; it++) Wreg[it] = wp[it * 8 + c];
    __syncthreads();

    for (int t = 0; t < NSTEP; t++) {
        // stage h (L1-bypass; prior barrier guarantees freshness in L2)
        {
            const float4* hp = ((const float4*)g_h[t & 1]) + tid;
            h_s[tid] = __ldcg(hp);
        }
        __syncthreads();

        ull a0 = 0, a1 = 0, a2 = 0, a3 = 0;
#pragma unroll
        for (int it = 0; it < 32; it++) {
            float4 h4 = h_s[it * 8 + c];  // broadcast, conflict-free
            float4 w4 = Wreg[it];
            ull hx = pack2(h4.x, h4.y);
            ull hy = pack2(h4.z, h4.w);
            ull wx = pack2(w4.x, w4.y);
            ull wy = pack2(w4.z, w4.w);
            if (it & 1) {
                ffma2(a2, wx, hx);
                ffma2(a3, wy, hy);
            } else {
                ffma2(a0, wx, hx);
                ffma2(a1, wy, hy);
            }
        }
        float sum = (sum2(a0) + sum2(a1)) + (sum2(a2) + sum2(a3));
        sum += __shfl_xor_sync(0xFFFFFFFFu, sum, 1);
        sum += __shfl_xor_sync(0xFFFFFFFFu, sum, 2);
        sum += __shfl_xor_sync(0xFFFFFFFFu, sum, 4);
        if (c == 0) sg[rid] = sum;
        __syncthreads();

        if (tid < 8) {
            const int j = tid;
            float vi = sg[0 * 8 + j] + sGin[t][0][j];
            float vf = sg[1 * 8 + j] + sGin[t][1][j];
            float vg = sg[2 * 8 + j] + sGin[t][2][j];
            float vo = sg[3 * 8 + j] + sGin[t][3][j];
            float ig = 1.f / (1.f + expf(-vi));
            float fg = 1.f / (1.f + expf(-vf));
            float gg = tanhf(vg);
            float og = 1.f / (1.f + expf(-vo));
            float cn = fg * c_s[j] + ig * gg;
            c_s[j] = cn;
            float hn = og * tanhf(cn);
            g_h[(t + 1) & 1][b * 8 + j] = hn;
            g_HS[(size_t)t * 1024 + b * 8 + j] = hn;
        }
        __syncthreads();  // all block writes done before release

        if (tid == 0) {
            red_release_add1(&g_arrive);  // release: publishes block's writes
            const unsigned target = (unsigned)NBLK * (unsigned)(t + 1);
            while (ld_acquire(&g_arrive) < target) {}
        }
        __syncthreads();
    }
}

// ---------------- launch ----------------
extern "C" void kernel_launch(void* const* d_in, const int* in_sizes, int n_in,
                              void* d_out, int out_size) {
    const int* sent = (const int*)d_in[0];
    const float* h0 = (const float*)d_in[1];
    const float* c0 = (const float*)d_in[2];
    const float* emb = (const float*)d_in[3];
    const float* Wih = (const float*)d_in[4];
    const float* Whh = (const float*)d_in[5];
    const float* bih = (const float*)d_in[6];
    const float* bhh = (const float*)d_in[7];
    const float* Wout = (const float*)d_in[8];
    const float* bout = (const float*)d_in[9];
    float* out = (float*)d_out;

    float* gX;
    float* gGin;
    float* gHS;
    float* gP;
    cudaGetSymbolAddress((void**)&gX, g_X);
    cudaGetSymbolAddress((void**)&gGin, g_Gin);
    cudaGetSymbolAddress((void**)&gHS, g_HS);
    cudaGetSymbolAddress((void**)&gP, g_P);

    // 1) gather inputs + init state + reset barrier
    prep_kernel<<<65, 256>>>(sent, emb, h0);

    // 2) input projection, split-K=4: partials then combine (+ biases)
    {
        dim3 grid(4096 / 128, 4);
        gemm_splitk<<<grid, 128>>>(gX, Wih, gP, 4096, 1024, 4096, 4);
        dim3 cgrid(4096 / 256, 50);
        combine_gin_kernel<<<cgrid, 256>>>(bih, bhh);
    }

    // 3) persistent recurrence (register-resident W_hh)
    lstm_persistent<<<NBLK, 256>>>(Whh, gGin, c0);

    // 4) output projection, split-K=2: partials then combine (+ bias)
    {
        dim3 grid(LDP_OUT / 128, 2);
        gemm_splitk<<<grid, 128>>>(gHS, Wout, gP, NOUT, 1024, LDP_OUT, 2);
        dim3 cgrid((NOUT + 255) / 256, 50);
        combine_out_kernel<<<cgrid, 256>>>(bout, out);
    }
}